// round 8
// baseline (speedup 1.0000x reference)
#include <cuda_runtime.h>
#include <cuda_fp16.h>
#include <cstdint>

#define BATCH   2048
#define NTOK    49
#define DIM     512
#define NHEAD   16
#define HDIM    32
#define NW      64
#define MROWS   (BATCH * NTOK)   // 100352 = 784 * 128
#define QKVCOLS (3 * DIM)        // 1536
#define KD      512

// Scratch (device globals — no cudaMalloc allowed)
__device__ __half g_xhi[(size_t)MROWS * KD];
__device__ __half g_xlo[(size_t)MROWS * KD];
__device__ __half g_wq[QKVCOLS * KD];
__device__ __half g_wp[DIM * KD];
__device__ float  g_qkv[(size_t)MROWS * QKVCOLS];
__device__ __half g_ahi[(size_t)MROWS * DIM];
__device__ __half g_alo[(size_t)MROWS * DIM];

// ---------------------------------------------------------------------------
// Helpers
// ---------------------------------------------------------------------------
__device__ __forceinline__ uint32_t smem_u32(const void* p) {
    uint32_t a;
    asm("{ .reg .u64 t; cvta.to.shared.u64 t, %1; cvt.u32.u64 %0, t; }"
        : "=r"(a) : "l"(p));
    return a;
}
__device__ __forceinline__ void cp16(uint32_t dst, const void* src) {
    asm volatile("cp.async.cg.shared.global [%0], [%1], 16;"
                 :: "r"(dst), "l"(src));
}
__device__ __forceinline__ void cp_commit() {
    asm volatile("cp.async.commit_group;" ::: "memory");
}
template <int N>
__device__ __forceinline__ void cp_wait() {
    asm volatile("cp.async.wait_group %0;" :: "n"(N) : "memory");
}
__device__ __forceinline__ void mma16816(float* c,
                                         uint32_t a0, uint32_t a1, uint32_t a2, uint32_t a3,
                                         uint32_t b0, uint32_t b1) {
    asm volatile(
        "mma.sync.aligned.m16n8k16.row.col.f32.f16.f16.f32 "
        "{%0,%1,%2,%3}, {%4,%5,%6,%7}, {%8,%9}, {%0,%1,%2,%3};"
        : "+f"(c[0]), "+f"(c[1]), "+f"(c[2]), "+f"(c[3])
        : "r"(a0), "r"(a1), "r"(a2), "r"(a3), "r"(b0), "r"(b1));
}

// ---------------------------------------------------------------------------
// Conversion kernels
// ---------------------------------------------------------------------------
__global__ void convert_x_kernel(const float* __restrict__ x,
                                 __half* __restrict__ hi,
                                 __half* __restrict__ lo, size_t n4) {
    size_t i = (size_t)blockIdx.x * blockDim.x + threadIdx.x;
    if (i >= n4) return;
    float4 v = ((const float4*)x)[i];
    __half h0 = __float2half_rn(v.x);
    __half h1 = __float2half_rn(v.y);
    __half h2 = __float2half_rn(v.z);
    __half h3 = __float2half_rn(v.w);
    __half2 hp0; hp0.x = h0; hp0.y = h1;
    __half2 hp1; hp1.x = h2; hp1.y = h3;
    ((__half2*)hi)[i * 2 + 0] = hp0;
    ((__half2*)hi)[i * 2 + 1] = hp1;
    __half2 lp0, lp1;
    lp0.x = __float2half_rn(v.x - __half2float(h0));
    lp0.y = __float2half_rn(v.y - __half2float(h1));
    lp1.x = __float2half_rn(v.z - __half2float(h2));
    lp1.y = __float2half_rn(v.w - __half2float(h3));
    ((__half2*)lo)[i * 2 + 0] = lp0;
    ((__half2*)lo)[i * 2 + 1] = lp1;
}

// w [K,N] fp32 -> fp16 [N,K] (transposed, hi only)
__global__ void convert_w_kernel(const float* __restrict__ w,
                                 __half* __restrict__ hi, int K, int N) {
    int idx = blockIdx.x * blockDim.x + threadIdx.x;
    if (idx >= K * N) return;
    int n = idx / K, k = idx - n * K;
    hi[idx] = __float2half_rn(w[(size_t)k * N + n]);
}

// ---------------------------------------------------------------------------
// Split-fp16 tensor-core GEMM (2-pass): C = (Ahi+Alo)[M,K] @ (B[N,K])^T + bias
// CTA tile 128x128, BK=32, 256 threads (8 warps, 4x2), warp tile 32x64.
// THREE-stage cp.async pipeline (each load gets 2 compute periods).
// ---------------------------------------------------------------------------
#define SM_STRIDE 80                 // bytes per smem row (32 fp16 + 8 pad)
#define SM_MAT    (128 * SM_STRIDE)  // 10240 B per matrix tile
#define SM_BUF    (3 * SM_MAT)       // AH, AL, BH = 30720 B per stage
#define GEMM_SMEM (3 * SM_BUF)       // 3 stages: 92160 B

__global__ void __launch_bounds__(256, 2)
gemm_mma(const __half* __restrict__ Ahi, const __half* __restrict__ Alo,
         const __half* __restrict__ Bh,
         const float* __restrict__ bias, float* __restrict__ C, int N) {
    extern __shared__ char sm[];
    const uint32_t smu = smem_u32(sm);

    const int tid  = threadIdx.x;
    const int lane = tid & 31;
    const int wid  = tid >> 5;
    const int wm   = wid & 3;          // 0..3 -> 32 rows each
    const int wn   = wid >> 2;         // 0..1 -> 64 cols each
    const int g    = lane >> 2;        // 0..7
    const int tg   = lane & 3;         // 0..3
    const int bn   = blockIdx.x, bm = blockIdx.y;

    const __half* A_h = Ahi + (size_t)bm * 128 * KD;
    const __half* A_l = Alo + (size_t)bm * 128 * KD;
    const __half* B_p = Bh  + (size_t)bn * 128 * KD;

    const int r0v = tid >> 2;
    const int r1v = (tid + 256) >> 2;
    const int c0v = (tid & 3) * 8;

    auto issue_tile = [&](int kt, int buf) {
        const int kof = kt * 32;
        const uint32_t sb = smu + buf * SM_BUF;
        const uint32_t o0 = (uint32_t)(r0v * SM_STRIDE + c0v * 2);
        const uint32_t o1 = (uint32_t)(r1v * SM_STRIDE + c0v * 2);
        const size_t g0 = (size_t)r0v * KD + kof + c0v;
        const size_t g1 = (size_t)r1v * KD + kof + c0v;
        cp16(sb + 0 * SM_MAT + o0, A_h + g0);
        cp16(sb + 0 * SM_MAT + o1, A_h + g1);
        cp16(sb + 1 * SM_MAT + o0, A_l + g0);
        cp16(sb + 1 * SM_MAT + o1, A_l + g1);
        cp16(sb + 2 * SM_MAT + o0, B_p + g0);
        cp16(sb + 2 * SM_MAT + o1, B_p + g1);
    };

    float acc[2][8][4];
    #pragma unroll
    for (int mt = 0; mt < 2; mt++)
        #pragma unroll
        for (int na = 0; na < 8; na++)
            #pragma unroll
            for (int r = 0; r < 4; r++) acc[mt][na][r] = 0.f;

    issue_tile(0, 0);
    cp_commit();
    issue_tile(1, 1);
    cp_commit();

    const int NKT = KD / 32;   // 16
    int buf = 0;
    for (int kt = 0; kt < NKT; kt++) {
        cp_wait<1>();          // tile kt complete (kt+1 may still be in flight)
        __syncthreads();       // all warps done reading stage (kt+2)%3 (at kt-1)
        if (kt + 2 < NKT) {
            issue_tile(kt + 2, (buf + 2 >= 3) ? buf - 1 : buf + 2);
            cp_commit();
        } else {
            // keep group accounting uniform so cp_wait<1> semantics hold
            cp_commit();
        }

        const char* sb = sm + buf * SM_BUF;
        const char* pAH = sb;
        const char* pAL = sb + SM_MAT;
        const char* pBH = sb + 2 * SM_MAT;
        const int m0 = wm * 32;
        const int n0 = wn * 64;

        #pragma unroll
        for (int ks = 0; ks < 32; ks += 16) {
            const int ko = (ks + tg * 2) * 2;
            uint32_t aH[2][4], aL[2][4];
            #pragma unroll
            for (int mt = 0; mt < 2; mt++) {
                const int rb = (m0 + mt * 16 + g) * SM_STRIDE;
                aH[mt][0] = *(const uint32_t*)(pAH + rb + ko);
                aH[mt][1] = *(const uint32_t*)(pAH + rb + 8 * SM_STRIDE + ko);
                aH[mt][2] = *(const uint32_t*)(pAH + rb + ko + 16);
                aH[mt][3] = *(const uint32_t*)(pAH + rb + 8 * SM_STRIDE + ko + 16);
                aL[mt][0] = *(const uint32_t*)(pAL + rb + ko);
                aL[mt][1] = *(const uint32_t*)(pAL + rb + 8 * SM_STRIDE + ko);
                aL[mt][2] = *(const uint32_t*)(pAL + rb + ko + 16);
                aL[mt][3] = *(const uint32_t*)(pAL + rb + 8 * SM_STRIDE + ko + 16);
            }
            #pragma unroll
            for (int na = 0; na < 8; na++) {
                const int nb = (n0 + na * 8 + g) * SM_STRIDE;
                const uint32_t b0 = *(const uint32_t*)(pBH + nb + ko);
                const uint32_t b1 = *(const uint32_t*)(pBH + nb + ko + 16);
                #pragma unroll
                for (int mt = 0; mt < 2; mt++) {
                    mma16816(acc[mt][na], aH[mt][0], aH[mt][1], aH[mt][2], aH[mt][3], b0, b1);
                    mma16816(acc[mt][na], aL[mt][0], aL[mt][1], aL[mt][2], aL[mt][3], b0, b1);
                }
            }
        }
        buf = (buf + 1 == 3) ? 0 : buf + 1;
    }

    // Epilogue: direct STG.64 with bias
    #pragma unroll
    for (int mt = 0; mt < 2; mt++) {
        const int row0 = bm * 128 + wm * 32 + mt * 16 + g;
        #pragma unroll
        for (int na = 0; na < 8; na++) {
            const int col = bn * 128 + wn * 64 + na * 8 + tg * 2;
            const float b0 = __ldg(bias + col);
            const float b1 = __ldg(bias + col + 1);
            float2 o0, o1;
            o0.x = acc[mt][na][0] + b0;
            o0.y = acc[mt][na][1] + b1;
            o1.x = acc[mt][na][2] + b0;
            o1.y = acc[mt][na][3] + b1;
            *(float2*)(C + (size_t)row0 * N + col) = o0;
            *(float2*)(C + (size_t)(row0 + 8) * N + col) = o1;
        }
    }
}

// ---------------------------------------------------------------------------
// Window attention — 4x4 register tiling, preloaded mask+bias, float4 smem.
// One block per (window b, head h), 128 threads.
// ---------------------------------------------------------------------------
__global__ __launch_bounds__(128)
void window_attn_kernel(const float* __restrict__ qkv,
                        const float* __restrict__ mask,
                        const float* __restrict__ bias_table,
                        __half* __restrict__ ohi,
                        __half* __restrict__ olo) {
    const int b = blockIdx.x;
    const int h = blockIdx.y;
    const int tid = threadIdx.x;
    const int lane = tid & 31;
    const int wid = tid >> 5;

    __shared__ float q[NTOK][HDIM];        // pre-scaled
    __shared__ float kT[HDIM][52];         // transposed, padded stride 52
    __shared__ float v[NTOK][HDIM];
    __shared__ float s[NTOK][52];          // scores (mask preloaded)
    __shared__ float sbias[169];           // rel-pos bias column for head h

    const float scale = rsqrtf((float)HDIM);
    const size_t col0 = (size_t)h * HDIM;

    for (int i = tid; i < 169; i += 128)
        sbias[i] = bias_table[i * NHEAD + h];

    for (int idx = tid; idx < NTOK * 8; idx += 128) {
        const int n = idx >> 3;
        const int c4 = (idx & 7) * 4;
        const float* rp = qkv + (size_t)(b * NTOK + n) * QKVCOLS + col0 + c4;
        float4 qv = *(const float4*)(rp);
        qv.x *= scale; qv.y *= scale; qv.z *= scale; qv.w *= scale;
        *(float4*)&q[n][c4] = qv;
        float4 kv = *(const float4*)(rp + DIM);
        kT[c4 + 0][n] = kv.x;
        kT[c4 + 1][n] = kv.y;
        kT[c4 + 2][n] = kv.z;
        kT[c4 + 3][n] = kv.w;
        *(float4*)&v[n][c4] = *(const float4*)(rp + 2 * DIM);
    }

    const float* mrow = mask + (size_t)(b & (NW - 1)) * NTOK * NTOK;
    for (int idx = tid; idx < NTOK * NTOK; idx += 128) {
        const int i = idx / NTOK;
        const int j = idx - i * NTOK;
        s[i][j] = mrow[idx];
    }
    __syncthreads();

    // QK^T: 13x13 tiles of 4x4
    for (int p = tid; p < 169; p += 128) {
        const int ti = p / 13;
        const int tj = p - ti * 13;
        const int i0 = ti * 4;
        const int j0 = tj * 4;
        const float* qp0 = q[i0];
        const float* qp1 = q[min(i0 + 1, NTOK - 1)];
        const float* qp2 = q[min(i0 + 2, NTOK - 1)];
        const float* qp3 = q[min(i0 + 3, NTOK - 1)];

        float acc[4][4];
        #pragma unroll
        for (int r = 0; r < 4; r++)
            #pragma unroll
            for (int c = 0; c < 4; c++) acc[r][c] = 0.f;

        #pragma unroll
        for (int d = 0; d < HDIM; d++) {
            const float4 kk = *(const float4*)&kT[d][j0];
            const float q0 = qp0[d], q1 = qp1[d], q2 = qp2[d], q3 = qp3[d];
            acc[0][0] = fmaf(q0, kk.x, acc[0][0]);
            acc[0][1] = fmaf(q0, kk.y, acc[0][1]);
            acc[0][2] = fmaf(q0, kk.z, acc[0][2]);
            acc[0][3] = fmaf(q0, kk.w, acc[0][3]);
            acc[1][0] = fmaf(q1, kk.x, acc[1][0]);
            acc[1][1] = fmaf(q1, kk.y, acc[1][1]);
            acc[1][2] = fmaf(q1, kk.z, acc[1][2]);
            acc[1][3] = fmaf(q1, kk.w, acc[1][3]);
            acc[2][0] = fmaf(q2, kk.x, acc[2][0]);
            acc[2][1] = fmaf(q2, kk.y, acc[2][1]);
            acc[2][2] = fmaf(q2, kk.z, acc[2][2]);
            acc[2][3] = fmaf(q2, kk.w, acc[2][3]);
            acc[3][0] = fmaf(q3, kk.x, acc[3][0]);
            acc[3][1] = fmaf(q3, kk.y, acc[3][1]);
            acc[3][2] = fmaf(q3, kk.z, acc[3][2]);
            acc[3][3] = fmaf(q3, kk.w, acc[3][3]);
        }

        #pragma unroll
        for (int r = 0; r < 4; r++) {
            const int i = i0 + r;
            if (i >= NTOK) break;
            const int yi = i / 7, xi = i - yi * 7;
            #pragma unroll
            for (int c = 0; c < 4; c++) {
                const int j = j0 + c;
                if (j >= NTOK) break;
                const int yj = j / 7, xj = j - yj * 7;
                const int rel = (yi - yj + 6) * 13 + (xi - xj + 6);
                s[i][j] += acc[r][c] + sbias[rel];
            }
        }
    }
    __syncthreads();

    for (int r = wid; r < NTOK; r += 4) {
        const bool v2 = (lane + 32 < NTOK);
        float x0 = s[r][lane];
        float x1 = v2 ? s[r][lane + 32] : -1e30f;
        float m = fmaxf(x0, x1);
        #pragma unroll
        for (int off = 16; off > 0; off >>= 1)
            m = fmaxf(m, __shfl_xor_sync(0xffffffffu, m, off));
        float e0 = __expf(x0 - m);
        float e1 = v2 ? __expf(x1 - m) : 0.f;
        float sum = e0 + e1;
        #pragma unroll
        for (int off = 16; off > 0; off >>= 1)
            sum += __shfl_xor_sync(0xffffffffu, sum, off);
        const float inv = 1.f / sum;
        s[r][lane] = e0 * inv;
        if (v2) s[r][lane + 32] = e1 * inv;
    }
    __syncthreads();

    // P @ V: 13x8 tiles of 4(i) x 4(d)
    if (tid < 104) {
        const int ti = tid >> 3;
        const int d0 = (tid & 7) * 4;
        const int i0 = ti * 4;
        const float* sp0 = s[i0];
        const float* sp1 = s[min(i0 + 1, NTOK - 1)];
        const float* sp2 = s[min(i0 + 2, NTOK - 1)];
        const float* sp3 = s[min(i0 + 3, NTOK - 1)];

        float acc[4][4];
        #pragma unroll
        for (int r = 0; r < 4; r++)
            #pragma unroll
            for (int c = 0; c < 4; c++) acc[r][c] = 0.f;

        #pragma unroll 7
        for (int j = 0; j < NTOK; j++) {
            const float4 vv = *(const float4*)&v[j][d0];
            const float s0 = sp0[j], s1 = sp1[j], s2 = sp2[j], s3 = sp3[j];
            acc[0][0] = fmaf(s0, vv.x, acc[0][0]);
            acc[0][1] = fmaf(s0, vv.y, acc[0][1]);
            acc[0][2] = fmaf(s0, vv.z, acc[0][2]);
            acc[0][3] = fmaf(s0, vv.w, acc[0][3]);
            acc[1][0] = fmaf(s1, vv.x, acc[1][0]);
            acc[1][1] = fmaf(s1, vv.y, acc[1][1]);
            acc[1][2] = fmaf(s1, vv.z, acc[1][2]);
            acc[1][3] = fmaf(s1, vv.w, acc[1][3]);
            acc[2][0] = fmaf(s2, vv.x, acc[2][0]);
            acc[2][1] = fmaf(s2, vv.y, acc[2][1]);
            acc[2][2] = fmaf(s2, vv.z, acc[2][2]);
            acc[2][3] = fmaf(s2, vv.w, acc[2][3]);
            acc[3][0] = fmaf(s3, vv.x, acc[3][0]);
            acc[3][1] = fmaf(s3, vv.y, acc[3][1]);
            acc[3][2] = fmaf(s3, vv.z, acc[3][2]);
            acc[3][3] = fmaf(s3, vv.w, acc[3][3]);
        }

        #pragma unroll
        for (int r = 0; r < 4; r++) {
            const int i = i0 + r;
            if (i >= NTOK) break;
            const size_t off = (size_t)(b * NTOK + i) * DIM + col0 + d0;
            __half2 h01, h23, l01, l23;
            h01.x = __float2half_rn(acc[r][0]);
            h01.y = __float2half_rn(acc[r][1]);
            h23.x = __float2half_rn(acc[r][2]);
            h23.y = __float2half_rn(acc[r][3]);
            l01.x = __float2half_rn(acc[r][0] - __half2float(h01.x));
            l01.y = __float2half_rn(acc[r][1] - __half2float(h01.y));
            l23.x = __float2half_rn(acc[r][2] - __half2float(h23.x));
            l23.y = __float2half_rn(acc[r][3] - __half2float(h23.y));
            *(__half2*)(ohi + off)     = h01;
            *(__half2*)(ohi + off + 2) = h23;
            *(__half2*)(olo + off)     = l01;
            *(__half2*)(olo + off + 2) = l23;
        }
    }
}

// ---------------------------------------------------------------------------
extern "C" void kernel_launch(void* const* d_in, const int* in_sizes, int n_in,
                              void* d_out, int out_size) {
    const float* x          = (const float*)d_in[0];
    const float* mask       = (const float*)d_in[1];
    const float* qkv_w      = (const float*)d_in[2];
    const float* qkv_b      = (const float*)d_in[3];
    const float* proj_w     = (const float*)d_in[4];
    const float* proj_b     = (const float*)d_in[5];
    const float* bias_table = (const float*)d_in[6];
    float* out = (float*)d_out;

    __half *xhi, *xlo, *wq, *wp, *ahi, *alo;
    float* qkvbuf;
    cudaGetSymbolAddress((void**)&xhi, g_xhi);
    cudaGetSymbolAddress((void**)&xlo, g_xlo);
    cudaGetSymbolAddress((void**)&wq, g_wq);
    cudaGetSymbolAddress((void**)&wp, g_wp);
    cudaGetSymbolAddress((void**)&ahi, g_ahi);
    cudaGetSymbolAddress((void**)&alo, g_alo);
    cudaGetSymbolAddress((void**)&qkvbuf, g_qkv);

    cudaFuncSetAttribute(gemm_mma, cudaFuncAttributeMaxDynamicSharedMemorySize,
                         GEMM_SMEM);

    {   // split x -> fp16 hi/lo
        const size_t n4 = (size_t)MROWS * KD / 4;
        convert_x_kernel<<<(unsigned)((n4 + 255) / 256), 256>>>(x, xhi, xlo, n4);
    }
    {   // weights: transpose + fp16
        convert_w_kernel<<<(KD * QKVCOLS + 255) / 256, 256>>>(qkv_w, wq, KD, QKVCOLS);
        convert_w_kernel<<<(KD * DIM + 255) / 256, 256>>>(proj_w, wp, KD, DIM);
    }
    {   // QKV GEMM (tensor cores)
        dim3 grid(QKVCOLS / 128, MROWS / 128);
        gemm_mma<<<grid, 256, GEMM_SMEM>>>(xhi, xlo, wq, qkv_b, qkvbuf, QKVCOLS);
    }
    {   // attention
        dim3 grid(BATCH, NHEAD);
        window_attn_kernel<<<grid, 128>>>(qkvbuf, mask, bias_table, ahi, alo);
    }
    {   // proj GEMM (tensor cores)
        dim3 grid(DIM / 128, MROWS / 128);
        gemm_mma<<<grid, 256, GEMM_SMEM>>>(ahi, alo, wp, proj_b, out, DIM);
    }
}

// round 9
// speedup vs baseline: 1.2846x; 1.2846x over previous
#include <cuda_runtime.h>
#include <cuda_fp16.h>
#include <cstdint>

#define BATCH   2048
#define NTOK    49
#define DIM     512
#define NHEAD   16
#define HDIM    32
#define NW      64
#define MROWS   (BATCH * NTOK)   // 100352 = 784 * 128
#define QKVCOLS (3 * DIM)        // 1536
#define KD      512

// Scratch (device globals — no cudaMalloc allowed)
__device__ __half g_xh[(size_t)MROWS * KD];
__device__ __half g_wq[QKVCOLS * KD];
__device__ __half g_wp[DIM * KD];
__device__ float  g_qkv[(size_t)MROWS * QKVCOLS];
__device__ __half g_ah[(size_t)MROWS * DIM];

// ---------------------------------------------------------------------------
// Helpers
// ---------------------------------------------------------------------------
__device__ __forceinline__ uint32_t smem_u32(const void* p) {
    uint32_t a;
    asm("{ .reg .u64 t; cvta.to.shared.u64 t, %1; cvt.u32.u64 %0, t; }"
        : "=r"(a) : "l"(p));
    return a;
}
__device__ __forceinline__ void cp16(uint32_t dst, const void* src) {
    asm volatile("cp.async.cg.shared.global [%0], [%1], 16;"
                 :: "r"(dst), "l"(src));
}
__device__ __forceinline__ void cp_commit() {
    asm volatile("cp.async.commit_group;" ::: "memory");
}
template <int N>
__device__ __forceinline__ void cp_wait() {
    asm volatile("cp.async.wait_group %0;" :: "n"(N) : "memory");
}
__device__ __forceinline__ void mma16816(float* c,
                                         uint32_t a0, uint32_t a1, uint32_t a2, uint32_t a3,
                                         uint32_t b0, uint32_t b1) {
    asm volatile(
        "mma.sync.aligned.m16n8k16.row.col.f32.f16.f16.f32 "
        "{%0,%1,%2,%3}, {%4,%5,%6,%7}, {%8,%9}, {%0,%1,%2,%3};"
        : "+f"(c[0]), "+f"(c[1]), "+f"(c[2]), "+f"(c[3])
        : "r"(a0), "r"(a1), "r"(a2), "r"(a3), "r"(b0), "r"(b1));
}

// ---------------------------------------------------------------------------
// Conversion kernels
// ---------------------------------------------------------------------------
__global__ void convert_x_kernel(const float* __restrict__ x,
                                 __half* __restrict__ hi, size_t n4) {
    size_t i = (size_t)blockIdx.x * blockDim.x + threadIdx.x;
    if (i >= n4) return;
    float4 v = ((const float4*)x)[i];
    __half2 hp0, hp1;
    hp0.x = __float2half_rn(v.x);
    hp0.y = __float2half_rn(v.y);
    hp1.x = __float2half_rn(v.z);
    hp1.y = __float2half_rn(v.w);
    ((__half2*)hi)[i * 2 + 0] = hp0;
    ((__half2*)hi)[i * 2 + 1] = hp1;
}

// w [K,N] fp32 -> fp16 [N,K] (transposed)
__global__ void convert_w_kernel(const float* __restrict__ w,
                                 __half* __restrict__ hi, int K, int N) {
    int idx = blockIdx.x * blockDim.x + threadIdx.x;
    if (idx >= K * N) return;
    int n = idx / K, k = idx - n * K;
    hi[idx] = __float2half_rn(w[(size_t)k * N + n]);
}

// ---------------------------------------------------------------------------
// Single-pass fp16 tensor-core GEMM: C = A[M,K] @ (B[N,K])^T + bias
// CTA tile 128x128, BK=32, 256 threads (8 warps, 4x2), warp tile 32x64.
// 2-stage cp.async pipeline; direct-LDS fragment loads (stride-80B smem).
// ---------------------------------------------------------------------------
#define SM_STRIDE 80                 // bytes per smem row (32 fp16 + 8 pad)
#define SM_MAT    (128 * SM_STRIDE)  // 10240 B per matrix tile
#define SM_BUF    (2 * SM_MAT)       // A, B = 20480 B per stage
#define GEMM_SMEM (2 * SM_BUF)       // 2 stages: 40960 B

__global__ void __launch_bounds__(256, 2)
gemm_mma(const __half* __restrict__ Ah, const __half* __restrict__ Bh,
         const float* __restrict__ bias, float* __restrict__ C, int N) {
    extern __shared__ char sm[];
    const uint32_t smu = smem_u32(sm);

    const int tid  = threadIdx.x;
    const int lane = tid & 31;
    const int wid  = tid >> 5;
    const int wm   = wid & 3;          // 0..3 -> 32 rows each
    const int wn   = wid >> 2;         // 0..1 -> 64 cols each
    const int g    = lane >> 2;        // 0..7
    const int tg   = lane & 3;         // 0..3
    const int bn   = blockIdx.x, bm = blockIdx.y;

    const __half* A_p = Ah + (size_t)bm * 128 * KD;
    const __half* B_p = Bh + (size_t)bn * 128 * KD;

    const int r0v = tid >> 2;
    const int r1v = (tid + 256) >> 2;
    const int c0v = (tid & 3) * 8;

    auto issue_tile = [&](int kt, int buf) {
        const int kof = kt * 32;
        const uint32_t sb = smu + buf * SM_BUF;
        const uint32_t o0 = (uint32_t)(r0v * SM_STRIDE + c0v * 2);
        const uint32_t o1 = (uint32_t)(r1v * SM_STRIDE + c0v * 2);
        const size_t g0 = (size_t)r0v * KD + kof + c0v;
        const size_t g1 = (size_t)r1v * KD + kof + c0v;
        cp16(sb + 0 * SM_MAT + o0, A_p + g0);
        cp16(sb + 0 * SM_MAT + o1, A_p + g1);
        cp16(sb + 1 * SM_MAT + o0, B_p + g0);
        cp16(sb + 1 * SM_MAT + o1, B_p + g1);
    };

    float acc[2][8][4];
    #pragma unroll
    for (int mt = 0; mt < 2; mt++)
        #pragma unroll
        for (int na = 0; na < 8; na++)
            #pragma unroll
            for (int r = 0; r < 4; r++) acc[mt][na][r] = 0.f;

    issue_tile(0, 0);
    cp_commit();

    const int NKT = KD / 32;   // 16
    for (int kt = 0; kt < NKT; kt++) {
        const int buf = kt & 1;
        if (kt + 1 < NKT) {
            issue_tile(kt + 1, buf ^ 1);
            cp_commit();
            cp_wait<1>();
        } else {
            cp_wait<0>();
        }
        __syncthreads();

        const char* sb = sm + buf * SM_BUF;
        const char* pA = sb;
        const char* pB = sb + SM_MAT;
        const int m0 = wm * 32;
        const int n0 = wn * 64;

        #pragma unroll
        for (int ks = 0; ks < 32; ks += 16) {
            const int ko = (ks + tg * 2) * 2;
            uint32_t a[2][4];
            #pragma unroll
            for (int mt = 0; mt < 2; mt++) {
                const int rb = (m0 + mt * 16 + g) * SM_STRIDE;
                a[mt][0] = *(const uint32_t*)(pA + rb + ko);
                a[mt][1] = *(const uint32_t*)(pA + rb + 8 * SM_STRIDE + ko);
                a[mt][2] = *(const uint32_t*)(pA + rb + ko + 16);
                a[mt][3] = *(const uint32_t*)(pA + rb + 8 * SM_STRIDE + ko + 16);
            }
            #pragma unroll
            for (int na = 0; na < 8; na++) {
                const int nb = (n0 + na * 8 + g) * SM_STRIDE;
                const uint32_t b0 = *(const uint32_t*)(pB + nb + ko);
                const uint32_t b1 = *(const uint32_t*)(pB + nb + ko + 16);
                #pragma unroll
                for (int mt = 0; mt < 2; mt++)
                    mma16816(acc[mt][na], a[mt][0], a[mt][1], a[mt][2], a[mt][3], b0, b1);
            }
        }
        __syncthreads();
    }

    // Epilogue: direct STG.64 with bias
    #pragma unroll
    for (int mt = 0; mt < 2; mt++) {
        const int row0 = bm * 128 + wm * 32 + mt * 16 + g;
        #pragma unroll
        for (int na = 0; na < 8; na++) {
            const int col = bn * 128 + wn * 64 + na * 8 + tg * 2;
            const float b0 = __ldg(bias + col);
            const float b1 = __ldg(bias + col + 1);
            float2 o0, o1;
            o0.x = acc[mt][na][0] + b0;
            o0.y = acc[mt][na][1] + b1;
            o1.x = acc[mt][na][2] + b0;
            o1.y = acc[mt][na][3] + b1;
            *(float2*)(C + (size_t)row0 * N + col) = o0;
            *(float2*)(C + (size_t)(row0 + 8) * N + col) = o1;
        }
    }
}

// ---------------------------------------------------------------------------
// Window attention — 4x4 register tiling, preloaded mask+bias, float4 smem.
// One block per (window b, head h), 128 threads. Emits fp16 for proj GEMM.
// ---------------------------------------------------------------------------
__global__ __launch_bounds__(128)
void window_attn_kernel(const float* __restrict__ qkv,
                        const float* __restrict__ mask,
                        const float* __restrict__ bias_table,
                        __half* __restrict__ oh) {
    const int b = blockIdx.x;
    const int h = blockIdx.y;
    const int tid = threadIdx.x;
    const int lane = tid & 31;
    const int wid = tid >> 5;

    __shared__ float q[NTOK][HDIM];        // pre-scaled
    __shared__ float kT[HDIM][52];         // transposed, padded stride 52
    __shared__ float v[NTOK][HDIM];
    __shared__ float s[NTOK][52];          // scores (mask preloaded)
    __shared__ float sbias[169];           // rel-pos bias column for head h

    const float scale = rsqrtf((float)HDIM);
    const size_t col0 = (size_t)h * HDIM;

    for (int i = tid; i < 169; i += 128)
        sbias[i] = bias_table[i * NHEAD + h];

    for (int idx = tid; idx < NTOK * 8; idx += 128) {
        const int n = idx >> 3;
        const int c4 = (idx & 7) * 4;
        const float* rp = qkv + (size_t)(b * NTOK + n) * QKVCOLS + col0 + c4;
        float4 qv = *(const float4*)(rp);
        qv.x *= scale; qv.y *= scale; qv.z *= scale; qv.w *= scale;
        *(float4*)&q[n][c4] = qv;
        float4 kv = *(const float4*)(rp + DIM);
        kT[c4 + 0][n] = kv.x;
        kT[c4 + 1][n] = kv.y;
        kT[c4 + 2][n] = kv.z;
        kT[c4 + 3][n] = kv.w;
        *(float4*)&v[n][c4] = *(const float4*)(rp + 2 * DIM);
    }

    const float* mrow = mask + (size_t)(b & (NW - 1)) * NTOK * NTOK;
    for (int idx = tid; idx < NTOK * NTOK; idx += 128) {
        const int i = idx / NTOK;
        const int j = idx - i * NTOK;
        s[i][j] = mrow[idx];
    }
    __syncthreads();

    // QK^T: 13x13 tiles of 4x4
    for (int p = tid; p < 169; p += 128) {
        const int ti = p / 13;
        const int tj = p - ti * 13;
        const int i0 = ti * 4;
        const int j0 = tj * 4;
        const float* qp0 = q[i0];
        const float* qp1 = q[min(i0 + 1, NTOK - 1)];
        const float* qp2 = q[min(i0 + 2, NTOK - 1)];
        const float* qp3 = q[min(i0 + 3, NTOK - 1)];

        float acc[4][4];
        #pragma unroll
        for (int r = 0; r < 4; r++)
            #pragma unroll
            for (int c = 0; c < 4; c++) acc[r][c] = 0.f;

        #pragma unroll
        for (int d = 0; d < HDIM; d++) {
            const float4 kk = *(const float4*)&kT[d][j0];
            const float q0 = qp0[d], q1 = qp1[d], q2 = qp2[d], q3 = qp3[d];
            acc[0][0] = fmaf(q0, kk.x, acc[0][0]);
            acc[0][1] = fmaf(q0, kk.y, acc[0][1]);
            acc[0][2] = fmaf(q0, kk.z, acc[0][2]);
            acc[0][3] = fmaf(q0, kk.w, acc[0][3]);
            acc[1][0] = fmaf(q1, kk.x, acc[1][0]);
            acc[1][1] = fmaf(q1, kk.y, acc[1][1]);
            acc[1][2] = fmaf(q1, kk.z, acc[1][2]);
            acc[1][3] = fmaf(q1, kk.w, acc[1][3]);
            acc[2][0] = fmaf(q2, kk.x, acc[2][0]);
            acc[2][1] = fmaf(q2, kk.y, acc[2][1]);
            acc[2][2] = fmaf(q2, kk.z, acc[2][2]);
            acc[2][3] = fmaf(q2, kk.w, acc[2][3]);
            acc[3][0] = fmaf(q3, kk.x, acc[3][0]);
            acc[3][1] = fmaf(q3, kk.y, acc[3][1]);
            acc[3][2] = fmaf(q3, kk.z, acc[3][2]);
            acc[3][3] = fmaf(q3, kk.w, acc[3][3]);
        }

        #pragma unroll
        for (int r = 0; r < 4; r++) {
            const int i = i0 + r;
            if (i >= NTOK) break;
            const int yi = i / 7, xi = i - yi * 7;
            #pragma unroll
            for (int c = 0; c < 4; c++) {
                const int j = j0 + c;
                if (j >= NTOK) break;
                const int yj = j / 7, xj = j - yj * 7;
                const int rel = (yi - yj + 6) * 13 + (xi - xj + 6);
                s[i][j] += acc[r][c] + sbias[rel];
            }
        }
    }
    __syncthreads();

    for (int r = wid; r < NTOK; r += 4) {
        const bool v2 = (lane + 32 < NTOK);
        float x0 = s[r][lane];
        float x1 = v2 ? s[r][lane + 32] : -1e30f;
        float m = fmaxf(x0, x1);
        #pragma unroll
        for (int off = 16; off > 0; off >>= 1)
            m = fmaxf(m, __shfl_xor_sync(0xffffffffu, m, off));
        float e0 = __expf(x0 - m);
        float e1 = v2 ? __expf(x1 - m) : 0.f;
        float sum = e0 + e1;
        #pragma unroll
        for (int off = 16; off > 0; off >>= 1)
            sum += __shfl_xor_sync(0xffffffffu, sum, off);
        const float inv = 1.f / sum;
        s[r][lane] = e0 * inv;
        if (v2) s[r][lane + 32] = e1 * inv;
    }
    __syncthreads();

    // P @ V: 13x8 tiles of 4(i) x 4(d)
    if (tid < 104) {
        const int ti = tid >> 3;
        const int d0 = (tid & 7) * 4;
        const int i0 = ti * 4;
        const float* sp0 = s[i0];
        const float* sp1 = s[min(i0 + 1, NTOK - 1)];
        const float* sp2 = s[min(i0 + 2, NTOK - 1)];
        const float* sp3 = s[min(i0 + 3, NTOK - 1)];

        float acc[4][4];
        #pragma unroll
        for (int r = 0; r < 4; r++)
            #pragma unroll
            for (int c = 0; c < 4; c++) acc[r][c] = 0.f;

        #pragma unroll 7
        for (int j = 0; j < NTOK; j++) {
            const float4 vv = *(const float4*)&v[j][d0];
            const float s0 = sp0[j], s1 = sp1[j], s2 = sp2[j], s3 = sp3[j];
            acc[0][0] = fmaf(s0, vv.x, acc[0][0]);
            acc[0][1] = fmaf(s0, vv.y, acc[0][1]);
            acc[0][2] = fmaf(s0, vv.z, acc[0][2]);
            acc[0][3] = fmaf(s0, vv.w, acc[0][3]);
            acc[1][0] = fmaf(s1, vv.x, acc[1][0]);
            acc[1][1] = fmaf(s1, vv.y, acc[1][1]);
            acc[1][2] = fmaf(s1, vv.z, acc[1][2]);
            acc[1][3] = fmaf(s1, vv.w, acc[1][3]);
            acc[2][0] = fmaf(s2, vv.x, acc[2][0]);
            acc[2][1] = fmaf(s2, vv.y, acc[2][1]);
            acc[2][2] = fmaf(s2, vv.z, acc[2][2]);
            acc[2][3] = fmaf(s2, vv.w, acc[2][3]);
            acc[3][0] = fmaf(s3, vv.x, acc[3][0]);
            acc[3][1] = fmaf(s3, vv.y, acc[3][1]);
            acc[3][2] = fmaf(s3, vv.z, acc[3][2]);
            acc[3][3] = fmaf(s3, vv.w, acc[3][3]);
        }

        #pragma unroll
        for (int r = 0; r < 4; r++) {
            const int i = i0 + r;
            if (i >= NTOK) break;
            const size_t off = (size_t)(b * NTOK + i) * DIM + col0 + d0;
            __half2 h01, h23;
            h01.x = __float2half_rn(acc[r][0]);
            h01.y = __float2half_rn(acc[r][1]);
            h23.x = __float2half_rn(acc[r][2]);
            h23.y = __float2half_rn(acc[r][3]);
            *(__half2*)(oh + off)     = h01;
            *(__half2*)(oh + off + 2) = h23;
        }
    }
}

// ---------------------------------------------------------------------------
extern "C" void kernel_launch(void* const* d_in, const int* in_sizes, int n_in,
                              void* d_out, int out_size) {
    const float* x          = (const float*)d_in[0];
    const float* mask       = (const float*)d_in[1];
    const float* qkv_w      = (const float*)d_in[2];
    const float* qkv_b      = (const float*)d_in[3];
    const float* proj_w     = (const float*)d_in[4];
    const float* proj_b     = (const float*)d_in[5];
    const float* bias_table = (const float*)d_in[6];
    float* out = (float*)d_out;

    __half *xh, *wq, *wp, *ah;
    float* qkvbuf;
    cudaGetSymbolAddress((void**)&xh, g_xh);
    cudaGetSymbolAddress((void**)&wq, g_wq);
    cudaGetSymbolAddress((void**)&wp, g_wp);
    cudaGetSymbolAddress((void**)&ah, g_ah);
    cudaGetSymbolAddress((void**)&qkvbuf, g_qkv);

    cudaFuncSetAttribute(gemm_mma, cudaFuncAttributeMaxDynamicSharedMemorySize,
                         GEMM_SMEM);

    {   // x -> fp16
        const size_t n4 = (size_t)MROWS * KD / 4;
        convert_x_kernel<<<(unsigned)((n4 + 255) / 256), 256>>>(x, xh, n4);
    }
    {   // weights: transpose + fp16
        convert_w_kernel<<<(KD * QKVCOLS + 255) / 256, 256>>>(qkv_w, wq, KD, QKVCOLS);
        convert_w_kernel<<<(KD * DIM + 255) / 256, 256>>>(proj_w, wp, KD, DIM);
    }
    {   // QKV GEMM (tensor cores)
        dim3 grid(QKVCOLS / 128, MROWS / 128);
        gemm_mma<<<grid, 256, GEMM_SMEM>>>(xh, wq, qkv_b, qkvbuf, QKVCOLS);
    }
    {   // attention
        dim3 grid(BATCH, NHEAD);
        window_attn_kernel<<<grid, 128>>>(qkvbuf, mask, bias_table, ah);
    }
    {   // proj GEMM (tensor cores)
        dim3 grid(DIM / 128, MROWS / 128);
        gemm_mma<<<grid, 256, GEMM_SMEM>>>(ah, wp, proj_b, out, DIM);
    }
}

// round 10
// speedup vs baseline: 1.3404x; 1.0434x over previous
#include <cuda_runtime.h>
#include <cuda_fp16.h>
#include <cstdint>

#define BATCH   2048
#define NTOK    49
#define DIM     512
#define NHEAD   16
#define HDIM    32
#define NW      64
#define MROWS   (BATCH * NTOK)   // 100352 = 784 * 128
#define QKVCOLS (3 * DIM)        // 1536
#define KD      512

// Scratch (device globals — no cudaMalloc allowed)
__device__ __half g_xh[(size_t)MROWS * KD];
__device__ __half g_wq[QKVCOLS * KD];
__device__ __half g_wp[DIM * KD];
__device__ float  g_qkv[(size_t)MROWS * QKVCOLS];
__device__ __half g_ah[(size_t)MROWS * DIM];

// ---------------------------------------------------------------------------
// Helpers
// ---------------------------------------------------------------------------
__device__ __forceinline__ uint32_t smem_u32(const void* p) {
    uint32_t a;
    asm("{ .reg .u64 t; cvta.to.shared.u64 t, %1; cvt.u32.u64 %0, t; }"
        : "=r"(a) : "l"(p));
    return a;
}
__device__ __forceinline__ void cp16(uint32_t dst, const void* src) {
    asm volatile("cp.async.cg.shared.global [%0], [%1], 16;"
                 :: "r"(dst), "l"(src));
}
__device__ __forceinline__ void cp_commit() {
    asm volatile("cp.async.commit_group;" ::: "memory");
}
template <int N>
__device__ __forceinline__ void cp_wait() {
    asm volatile("cp.async.wait_group %0;" :: "n"(N) : "memory");
}
__device__ __forceinline__ void mma16816(float* c,
                                         uint32_t a0, uint32_t a1, uint32_t a2, uint32_t a3,
                                         uint32_t b0, uint32_t b1) {
    asm volatile(
        "mma.sync.aligned.m16n8k16.row.col.f32.f16.f16.f32 "
        "{%0,%1,%2,%3}, {%4,%5,%6,%7}, {%8,%9}, {%0,%1,%2,%3};"
        : "+f"(c[0]), "+f"(c[1]), "+f"(c[2]), "+f"(c[3])
        : "r"(a0), "r"(a1), "r"(a2), "r"(a3), "r"(b0), "r"(b1));
}

// ---------------------------------------------------------------------------
// Conversion kernels
// ---------------------------------------------------------------------------
__global__ void convert_x_kernel(const float* __restrict__ x,
                                 __half* __restrict__ hi, size_t n4) {
    size_t i = (size_t)blockIdx.x * blockDim.x + threadIdx.x;
    if (i >= n4) return;
    float4 v = ((const float4*)x)[i];
    __half2 hp0, hp1;
    hp0.x = __float2half_rn(v.x);
    hp0.y = __float2half_rn(v.y);
    hp1.x = __float2half_rn(v.z);
    hp1.y = __float2half_rn(v.w);
    ((__half2*)hi)[i * 2 + 0] = hp0;
    ((__half2*)hi)[i * 2 + 1] = hp1;
}

// w [K,N] fp32 -> fp16 [N,K] (transposed)
__global__ void convert_w_kernel(const float* __restrict__ w,
                                 __half* __restrict__ hi, int K, int N) {
    int idx = blockIdx.x * blockDim.x + threadIdx.x;
    if (idx >= K * N) return;
    int n = idx / K, k = idx - n * K;
    hi[idx] = __float2half_rn(w[(size_t)k * N + n]);
}

// ---------------------------------------------------------------------------
// Single-pass fp16 tensor-core GEMM: C = A[M,K] @ (B[N,K])^T + bias
// CTA tile 128x128, BK=64, 256 threads (8 warps, 4x2), warp tile 32x64.
// 2-stage cp.async pipeline; direct-LDS fragment loads (stride-144B smem,
// conflict-free: bank = 4*g + tg covers 0..31).
// ---------------------------------------------------------------------------
#define SM_STRIDE 144                // bytes per smem row (64 fp16 + 16 pad)
#define SM_MAT    (128 * SM_STRIDE)  // 18432 B per matrix tile
#define SM_BUF    (2 * SM_MAT)       // A, B = 36864 B per stage
#define GEMM_SMEM (2 * SM_BUF)       // 2 stages: 73728 B

__global__ void __launch_bounds__(256, 2)
gemm_mma(const __half* __restrict__ Ah, const __half* __restrict__ Bh,
         const float* __restrict__ bias, float* __restrict__ C, int N) {
    extern __shared__ char sm[];
    const uint32_t smu = smem_u32(sm);

    const int tid  = threadIdx.x;
    const int lane = tid & 31;
    const int wid  = tid >> 5;
    const int wm   = wid & 3;          // 0..3 -> 32 rows each
    const int wn   = wid >> 2;         // 0..1 -> 64 cols each
    const int g    = lane >> 2;        // 0..7
    const int tg   = lane & 3;         // 0..3
    const int bn   = blockIdx.x, bm = blockIdx.y;

    const __half* A_p = Ah + (size_t)bm * 128 * KD;
    const __half* B_p = Bh + (size_t)bn * 128 * KD;

    // cp.async for one 128x64 tile: 128 rows x 128 B = 1024 x cp16 per matrix
    auto issue_tile = [&](int kt, int buf) {
        const int kof = kt * 64;
        const uint32_t sb = smu + buf * SM_BUF;
        #pragma unroll
        for (int i = 0; i < 4; i++) {
            const int u = tid + i * 256;
            const int row = u >> 3;
            const int c8 = (u & 7) * 8;
            const uint32_t off = (uint32_t)(row * SM_STRIDE + c8 * 2);
            const size_t go = (size_t)row * KD + kof + c8;
            cp16(sb + off, A_p + go);
            cp16(sb + SM_MAT + off, B_p + go);
        }
    };

    float acc[2][8][4];
    #pragma unroll
    for (int mt = 0; mt < 2; mt++)
        #pragma unroll
        for (int na = 0; na < 8; na++)
            #pragma unroll
            for (int r = 0; r < 4; r++) acc[mt][na][r] = 0.f;

    issue_tile(0, 0);
    cp_commit();

    const int NKT = KD / 64;   // 8
    for (int kt = 0; kt < NKT; kt++) {
        const int buf = kt & 1;
        if (kt + 1 < NKT) {
            issue_tile(kt + 1, buf ^ 1);
            cp_commit();
            cp_wait<1>();
        } else {
            cp_wait<0>();
        }
        __syncthreads();

        const char* sb = sm + buf * SM_BUF;
        const char* pA = sb;
        const char* pB = sb + SM_MAT;
        const int m0 = wm * 32;
        const int n0 = wn * 64;

        #pragma unroll
        for (int ks = 0; ks < 64; ks += 16) {
            const int ko = (ks + tg * 2) * 2;
            uint32_t a[2][4];
            #pragma unroll
            for (int mt = 0; mt < 2; mt++) {
                const int rb = (m0 + mt * 16 + g) * SM_STRIDE;
                a[mt][0] = *(const uint32_t*)(pA + rb + ko);
                a[mt][1] = *(const uint32_t*)(pA + rb + 8 * SM_STRIDE + ko);
                a[mt][2] = *(const uint32_t*)(pA + rb + ko + 16);
                a[mt][3] = *(const uint32_t*)(pA + rb + 8 * SM_STRIDE + ko + 16);
            }
            #pragma unroll
            for (int na = 0; na < 8; na++) {
                const int nb = (n0 + na * 8 + g) * SM_STRIDE;
                const uint32_t b0 = *(const uint32_t*)(pB + nb + ko);
                const uint32_t b1 = *(const uint32_t*)(pB + nb + ko + 16);
                #pragma unroll
                for (int mt = 0; mt < 2; mt++)
                    mma16816(acc[mt][na], a[mt][0], a[mt][1], a[mt][2], a[mt][3], b0, b1);
            }
        }
        __syncthreads();
    }

    // Epilogue: direct STG.64 with bias
    #pragma unroll
    for (int mt = 0; mt < 2; mt++) {
        const int row0 = bm * 128 + wm * 32 + mt * 16 + g;
        #pragma unroll
        for (int na = 0; na < 8; na++) {
            const int col = bn * 128 + wn * 64 + na * 8 + tg * 2;
            const float b0 = __ldg(bias + col);
            const float b1 = __ldg(bias + col + 1);
            float2 o0, o1;
            o0.x = acc[mt][na][0] + b0;
            o0.y = acc[mt][na][1] + b1;
            o1.x = acc[mt][na][2] + b0;
            o1.y = acc[mt][na][3] + b1;
            *(float2*)(C + (size_t)row0 * N + col) = o0;
            *(float2*)(C + (size_t)(row0 + 8) * N + col) = o1;
        }
    }
}

// ---------------------------------------------------------------------------
// Window attention — qT/kT both transposed (float4 fragment loads), QK 4x8
// tiles (91 items, single pass), PV 4x4. Emits fp16 for proj GEMM.
// ---------------------------------------------------------------------------
__global__ __launch_bounds__(128)
void window_attn_kernel(const float* __restrict__ qkv,
                        const float* __restrict__ mask,
                        const float* __restrict__ bias_table,
                        __half* __restrict__ oh) {
    const int b = blockIdx.x;
    const int h = blockIdx.y;
    const int tid = threadIdx.x;
    const int lane = tid & 31;
    const int wid = tid >> 5;

    __shared__ float qT[HDIM][52];         // transposed, pre-scaled (pad 52)
    __shared__ float kT[HDIM][56];         // transposed (pad 56 for 8-wide tiles)
    __shared__ float v[NTOK][HDIM];
    __shared__ float s[NTOK][52];          // scores (mask preloaded)
    __shared__ float sbias[169];           // rel-pos bias column for head h

    const float scale = rsqrtf((float)HDIM);
    const size_t col0 = (size_t)h * HDIM;

    for (int i = tid; i < 169; i += 128)
        sbias[i] = bias_table[i * NHEAD + h];

    // zero the tile padding so junk never reaches the FMAs
    if (tid < HDIM) {
        qT[tid][49] = 0.f; qT[tid][50] = 0.f; qT[tid][51] = 0.f;
        #pragma unroll
        for (int j = 49; j < 56; j++) kT[tid][j] = 0.f;
    }

    for (int idx = tid; idx < NTOK * 8; idx += 128) {
        const int n = idx >> 3;
        const int c4 = (idx & 7) * 4;
        const float* rp = qkv + (size_t)(b * NTOK + n) * QKVCOLS + col0 + c4;
        float4 qv = *(const float4*)(rp);
        qT[c4 + 0][n] = qv.x * scale;
        qT[c4 + 1][n] = qv.y * scale;
        qT[c4 + 2][n] = qv.z * scale;
        qT[c4 + 3][n] = qv.w * scale;
        float4 kv = *(const float4*)(rp + DIM);
        kT[c4 + 0][n] = kv.x;
        kT[c4 + 1][n] = kv.y;
        kT[c4 + 2][n] = kv.z;
        kT[c4 + 3][n] = kv.w;
        *(float4*)&v[n][c4] = *(const float4*)(rp + 2 * DIM);
    }

    const float* mrow = mask + (size_t)(b & (NW - 1)) * NTOK * NTOK;
    for (int idx = tid; idx < NTOK * NTOK; idx += 128) {
        const int i = idx / NTOK;
        const int j = idx - i * NTOK;
        s[i][j] = mrow[idx];
    }
    __syncthreads();

    // QK^T: 13(i) x 7(j) tiles of 4x8, single pass (91 items)
    if (tid < 91) {
        const int ti = tid / 7;
        const int tj = tid - ti * 7;
        const int i0 = ti * 4;
        const int j0 = tj * 8;

        float acc[4][8];
        #pragma unroll
        for (int r = 0; r < 4; r++)
            #pragma unroll
            for (int c = 0; c < 8; c++) acc[r][c] = 0.f;

        #pragma unroll
        for (int d = 0; d < HDIM; d++) {
            const float4 qq = *(const float4*)&qT[d][i0];
            const float4 k0 = *(const float4*)&kT[d][j0];
            const float4 k1 = *(const float4*)&kT[d][j0 + 4];
            const float qr[4] = {qq.x, qq.y, qq.z, qq.w};
            const float kc[8] = {k0.x, k0.y, k0.z, k0.w, k1.x, k1.y, k1.z, k1.w};
            #pragma unroll
            for (int r = 0; r < 4; r++)
                #pragma unroll
                for (int c = 0; c < 8; c++)
                    acc[r][c] = fmaf(qr[r], kc[c], acc[r][c]);
        }

        #pragma unroll
        for (int r = 0; r < 4; r++) {
            const int i = i0 + r;
            if (i >= NTOK) break;
            const int yi = i / 7, xi = i - yi * 7;
            #pragma unroll
            for (int c = 0; c < 8; c++) {
                const int j = j0 + c;
                if (j >= NTOK) break;
                const int yj = j / 7, xj = j - yj * 7;
                const int rel = (yi - yj + 6) * 13 + (xi - xj + 6);
                s[i][j] += acc[r][c] + sbias[rel];
            }
        }
    }
    __syncthreads();

    // Warp-parallel softmax: one warp per row
    for (int r = wid; r < NTOK; r += 4) {
        const bool v2 = (lane + 32 < NTOK);
        float x0 = s[r][lane];
        float x1 = v2 ? s[r][lane + 32] : -1e30f;
        float m = fmaxf(x0, x1);
        #pragma unroll
        for (int off = 16; off > 0; off >>= 1)
            m = fmaxf(m, __shfl_xor_sync(0xffffffffu, m, off));
        float e0 = __expf(x0 - m);
        float e1 = v2 ? __expf(x1 - m) : 0.f;
        float sum = e0 + e1;
        #pragma unroll
        for (int off = 16; off > 0; off >>= 1)
            sum += __shfl_xor_sync(0xffffffffu, sum, off);
        const float inv = 1.f / sum;
        s[r][lane] = e0 * inv;
        if (v2) s[r][lane + 32] = e1 * inv;
    }
    __syncthreads();

    // P @ V: 13x8 tiles of 4(i) x 4(d)
    if (tid < 104) {
        const int ti = tid >> 3;
        const int d0 = (tid & 7) * 4;
        const int i0 = ti * 4;
        const float* sp0 = s[i0];
        const float* sp1 = s[min(i0 + 1, NTOK - 1)];
        const float* sp2 = s[min(i0 + 2, NTOK - 1)];
        const float* sp3 = s[min(i0 + 3, NTOK - 1)];

        float acc[4][4];
        #pragma unroll
        for (int r = 0; r < 4; r++)
            #pragma unroll
            for (int c = 0; c < 4; c++) acc[r][c] = 0.f;

        #pragma unroll 7
        for (int j = 0; j < NTOK; j++) {
            const float4 vv = *(const float4*)&v[j][d0];
            const float s0 = sp0[j], s1 = sp1[j], s2 = sp2[j], s3 = sp3[j];
            acc[0][0] = fmaf(s0, vv.x, acc[0][0]);
            acc[0][1] = fmaf(s0, vv.y, acc[0][1]);
            acc[0][2] = fmaf(s0, vv.z, acc[0][2]);
            acc[0][3] = fmaf(s0, vv.w, acc[0][3]);
            acc[1][0] = fmaf(s1, vv.x, acc[1][0]);
            acc[1][1] = fmaf(s1, vv.y, acc[1][1]);
            acc[1][2] = fmaf(s1, vv.z, acc[1][2]);
            acc[1][3] = fmaf(s1, vv.w, acc[1][3]);
            acc[2][0] = fmaf(s2, vv.x, acc[2][0]);
            acc[2][1] = fmaf(s2, vv.y, acc[2][1]);
            acc[2][2] = fmaf(s2, vv.z, acc[2][2]);
            acc[2][3] = fmaf(s2, vv.w, acc[2][3]);
            acc[3][0] = fmaf(s3, vv.x, acc[3][0]);
            acc[3][1] = fmaf(s3, vv.y, acc[3][1]);
            acc[3][2] = fmaf(s3, vv.z, acc[3][2]);
            acc[3][3] = fmaf(s3, vv.w, acc[3][3]);
        }

        #pragma unroll
        for (int r = 0; r < 4; r++) {
            const int i = i0 + r;
            if (i >= NTOK) break;
            const size_t off = (size_t)(b * NTOK + i) * DIM + col0 + d0;
            __half2 h01, h23;
            h01.x = __float2half_rn(acc[r][0]);
            h01.y = __float2half_rn(acc[r][1]);
            h23.x = __float2half_rn(acc[r][2]);
            h23.y = __float2half_rn(acc[r][3]);
            *(__half2*)(oh + off)     = h01;
            *(__half2*)(oh + off + 2) = h23;
        }
    }
}

// ---------------------------------------------------------------------------
extern "C" void kernel_launch(void* const* d_in, const int* in_sizes, int n_in,
                              void* d_out, int out_size) {
    const float* x          = (const float*)d_in[0];
    const float* mask       = (const float*)d_in[1];
    const float* qkv_w      = (const float*)d_in[2];
    const float* qkv_b      = (const float*)d_in[3];
    const float* proj_w     = (const float*)d_in[4];
    const float* proj_b     = (const float*)d_in[5];
    const float* bias_table = (const float*)d_in[6];
    float* out = (float*)d_out;

    __half *xh, *wq, *wp, *ah;
    float* qkvbuf;
    cudaGetSymbolAddress((void**)&xh, g_xh);
    cudaGetSymbolAddress((void**)&wq, g_wq);
    cudaGetSymbolAddress((void**)&wp, g_wp);
    cudaGetSymbolAddress((void**)&ah, g_ah);
    cudaGetSymbolAddress((void**)&qkvbuf, g_qkv);

    cudaFuncSetAttribute(gemm_mma, cudaFuncAttributeMaxDynamicSharedMemorySize,
                         GEMM_SMEM);

    {   // x -> fp16
        const size_t n4 = (size_t)MROWS * KD / 4;
        convert_x_kernel<<<(unsigned)((n4 + 255) / 256), 256>>>(x, xh, n4);
    }
    {   // weights: transpose + fp16
        convert_w_kernel<<<(KD * QKVCOLS + 255) / 256, 256>>>(qkv_w, wq, KD, QKVCOLS);
        convert_w_kernel<<<(KD * DIM + 255) / 256, 256>>>(proj_w, wp, KD, DIM);
    }
    {   // QKV GEMM (tensor cores)
        dim3 grid(QKVCOLS / 128, MROWS / 128);
        gemm_mma<<<grid, 256, GEMM_SMEM>>>(xh, wq, qkv_b, qkvbuf, QKVCOLS);
    }
    {   // attention
        dim3 grid(BATCH, NHEAD);
        window_attn_kernel<<<grid, 128>>>(qkvbuf, mask, bias_table, ah);
    }
    {   // proj GEMM (tensor cores)
        dim3 grid(DIM / 128, MROWS / 128);
        gemm_mma<<<grid, 256, GEMM_SMEM>>>(ah, wp, proj_b, out, DIM);
    }
}